// round 7
// baseline (speedup 1.0000x reference)
#include <cuda_runtime.h>
#include <cuda_bf16.h>

#define BB 32
#define HH 4
#define SS 4096
#define MM 128

typedef unsigned long long u64;

__device__ __forceinline__ u64 fma2(u64 a, u64 b, u64 c) {
    u64 d; asm("fma.rn.f32x2 %0,%1,%2,%3;" : "=l"(d) : "l"(a), "l"(b), "l"(c)); return d;
}
__device__ __forceinline__ u64 mul2(u64 a, u64 b) {
    u64 d; asm("mul.rn.f32x2 %0,%1,%2;" : "=l"(d) : "l"(a), "l"(b)); return d;
}
__device__ __forceinline__ u64 pack2(float lo, float hi) {
    u64 r; asm("mov.b64 %0,{%1,%2};" : "=l"(r) : "f"(lo), "f"(hi)); return r;
}
__device__ __forceinline__ float2 unpack2(u64 x) {
    float2 f; asm("mov.b64 {%0,%1},%2;" : "=f"(f.x), "=f"(f.y) : "l"(x)); return f;
}
__device__ __forceinline__ float hadd2(u64 x) {
    const float2 f = unpack2(x); return f.x + f.y;
}

// Scratch
__device__ float4 g_w[BB * SS];        // logits, then softmax weights [b][s] x4 heads
__device__ float4 g_pm[BB * 32];       // per-tile max (4 heads)
__device__ float4 g_ps[BB * 32];       // per-tile expsum (4 heads)

// ---------------------------------------------------------------------------
// Kernel 1: R4's 8-lane/row quad structure, k in SMEM (broadcast LDS),
// logits scaled in-place, per-tile softmax partials (max, expsum) emitted.
// ---------------------------------------------------------------------------
__global__ void __launch_bounds__(256, 3) k1_dots(const float* __restrict__ mem,
                                                  const float* __restrict__ kq,
                                                  const float* __restrict__ beta) {
    const int b    = blockIdx.x >> 5;        // 32 tiles per b
    const int tile = blockIdx.x & 31;        // 128 rows per tile
    const int tid  = threadIdx.x;
    const int warp = tid >> 5;
    const int lane = tid & 31;
    const int l8   = lane & 7;
    const int r    = lane >> 3;

    __shared__ float  ksh[HH * MM];          // 512 floats
    __shared__ float  scl[HH];
    __shared__ float4 red[256];

    // k into shared (coalesced)
    ksh[tid]       = kq[b * HH * MM + tid];
    ksh[tid + 256] = kq[b * HH * MM + tid + 256];

    // per-head scale = beta / max(||k_h||, eps)   (warps 0..3)
    if (warp < HH) {
        const float4 kv = ((const float4*)(kq + (b * HH + warp) * MM))[lane];
        float ss = kv.x * kv.x + kv.y * kv.y + kv.z * kv.z + kv.w * kv.w;
#pragma unroll
        for (int o = 16; o > 0; o >>= 1)
            ss += __shfl_xor_sync(0xFFFFFFFFu, ss, o);
        if (lane == 0)
            scl[warp] = beta[b * HH + warp] / fmaxf(sqrtf(ss), 1e-8f);
    }
    __syncthreads();

    const float4 sc = make_float4(scl[0], scl[1], scl[2], scl[3]);

    // rows: s = tile*128 + warp*4 + r + q*32, q = 0..3
    const int srow0 = tile * 128 + warp * 4 + r;
    const float* base = mem + ((size_t)b * SS + srow0) * MM + l8 * 4;

    ulonglong2 vn[4];
#pragma unroll
    for (int j = 0; j < 4; ++j)
        vn[j] = *(const ulonglong2*)(base + j * 32);

    float4 lg[4];                            // this thread's quad logits

#pragma unroll
    for (int q = 0; q < 4; ++q) {
        ulonglong2 vc[4];
#pragma unroll
        for (int j = 0; j < 4; ++j) vc[j] = vn[j];
        if (q < 3) {
            const float* nb = base + (size_t)(q + 1) * 32 * MM;
#pragma unroll
            for (int j = 0; j < 4; ++j)
                vn[j] = *(const ulonglong2*)(nb + j * 32);
        }

        u64 ss2 = 0, d2[HH] = {0, 0, 0, 0};
#pragma unroll
        for (int j = 0; j < 4; ++j) {
            ss2 = fma2(vc[j].x, vc[j].x, ss2);
            ss2 = fma2(vc[j].y, vc[j].y, ss2);
#pragma unroll
            for (int h = 0; h < HH; ++h) {
                const ulonglong2 kk = *(const ulonglong2*)&ksh[h * MM + j * 32 + l8 * 4];
                d2[h] = fma2(vc[j].x, kk.x, d2[h]);
                d2[h] = fma2(vc[j].y, kk.y, d2[h]);
            }
        }

        float ssum = hadd2(ss2);
        float sd[HH];
#pragma unroll
        for (int h = 0; h < HH; ++h) sd[h] = hadd2(d2[h]);

#pragma unroll
        for (int o = 4; o > 0; o >>= 1) {
            ssum += __shfl_xor_sync(0xFFFFFFFFu, ssum, o);
#pragma unroll
            for (int h = 0; h < HH; ++h)
                sd[h] += __shfl_xor_sync(0xFFFFFFFFu, sd[h], o);
        }

        const float rmn = 1.0f / fmaxf(sqrtf(ssum), 1e-8f);
        lg[q] = make_float4(sd[0] * rmn * sc.x, sd[1] * rmn * sc.y,
                            sd[2] * rmn * sc.z, sd[3] * rmn * sc.w);
        if (l8 == 0)
            g_w[b * SS + srow0 + q * 32] = lg[q];
    }

    // ---- block softmax partials over this tile's 128 rows ----
    float4 mx = lg[0];
#pragma unroll
    for (int q = 1; q < 4; ++q) {
        mx.x = fmaxf(mx.x, lg[q].x); mx.y = fmaxf(mx.y, lg[q].y);
        mx.z = fmaxf(mx.z, lg[q].z); mx.w = fmaxf(mx.w, lg[q].w);
    }
    red[tid] = mx; __syncthreads();
#pragma unroll
    for (int o = 128; o > 0; o >>= 1) {
        if (tid < o) {
            float4 a = red[tid], c = red[tid + o];
            red[tid] = make_float4(fmaxf(a.x, c.x), fmaxf(a.y, c.y),
                                   fmaxf(a.z, c.z), fmaxf(a.w, c.w));
        }
        __syncthreads();
    }
    mx = red[0];
    __syncthreads();

    float4 es = make_float4(0, 0, 0, 0);
    if (l8 == 0) {
#pragma unroll
        for (int q = 0; q < 4; ++q) {
            es.x += __expf(lg[q].x - mx.x);
            es.y += __expf(lg[q].y - mx.y);
            es.z += __expf(lg[q].z - mx.z);
            es.w += __expf(lg[q].w - mx.w);
        }
    }
    red[tid] = es; __syncthreads();
#pragma unroll
    for (int o = 128; o > 0; o >>= 1) {
        if (tid < o) {
            float4 a = red[tid], c = red[tid + o];
            red[tid] = make_float4(a.x + c.x, a.y + c.y, a.z + c.z, a.w + c.w);
        }
        __syncthreads();
    }
    if (tid == 0) {
        g_pm[b * 32 + tile] = mx;
        g_ps[b * 32 + tile] = red[0];
    }
}

// ---------------------------------------------------------------------------
// Kernel 2: normalize. grid 256 (8 chunks x 32 b), 512 threads.
// Combines 32 tile partials, then w = exp(logit - m*) / S. Zeroes out.
// ---------------------------------------------------------------------------
__global__ void __launch_bounds__(512) k2_norm(float* __restrict__ out) {
    const int b     = blockIdx.x >> 3;
    const int chunk = blockIdx.x & 7;
    const int tid   = threadIdx.x;

    __shared__ float4 sm_m, sm_is;

    if (tid < 32) {
        float4 m4 = g_pm[b * 32 + tid];
        float4 s4 = g_ps[b * 32 + tid];
        float4 m = m4;
#pragma unroll
        for (int o = 16; o > 0; o >>= 1) {
            m.x = fmaxf(m.x, __shfl_xor_sync(0xFFFFFFFFu, m.x, o));
            m.y = fmaxf(m.y, __shfl_xor_sync(0xFFFFFFFFu, m.y, o));
            m.z = fmaxf(m.z, __shfl_xor_sync(0xFFFFFFFFu, m.z, o));
            m.w = fmaxf(m.w, __shfl_xor_sync(0xFFFFFFFFu, m.w, o));
        }
        float4 s;
        s.x = s4.x * __expf(m4.x - m.x);
        s.y = s4.y * __expf(m4.y - m.y);
        s.z = s4.z * __expf(m4.z - m.z);
        s.w = s4.w * __expf(m4.w - m.w);
#pragma unroll
        for (int o = 16; o > 0; o >>= 1) {
            s.x += __shfl_xor_sync(0xFFFFFFFFu, s.x, o);
            s.y += __shfl_xor_sync(0xFFFFFFFFu, s.y, o);
            s.z += __shfl_xor_sync(0xFFFFFFFFu, s.z, o);
            s.w += __shfl_xor_sync(0xFFFFFFFFu, s.w, o);
        }
        if (tid == 0) {
            sm_m  = m;
            sm_is = make_float4(1.0f / s.x, 1.0f / s.y, 1.0f / s.z, 1.0f / s.w);
        }
    }
    __syncthreads();

    const float4 m  = sm_m;
    const float4 is = sm_is;
    const int idx = b * SS + chunk * 512 + tid;
    float4 lg = g_w[idx];
    lg.x = __expf(lg.x - m.x) * is.x;
    lg.y = __expf(lg.y - m.y) * is.y;
    lg.z = __expf(lg.z - m.z) * is.z;
    lg.w = __expf(lg.w - m.w) * is.w;
    g_w[idx] = lg;

    if (chunk == 0)
        out[b * HH * MM + tid] = 0.0f;
}

// ---------------------------------------------------------------------------
// Kernel 3: fused write + read (verbatim from the proven R4 version).
// ---------------------------------------------------------------------------
#define NCHUNK 32
#define ROWS_PER_CHUNK (SS / NCHUNK)   // 128

__global__ void __launch_bounds__(256) k3_write_read(const float* __restrict__ mem,
                                                     const float* __restrict__ erase,
                                                     const float* __restrict__ add,
                                                     float* __restrict__ out) {
    const int b  = blockIdx.y;
    const int s0 = blockIdx.x * ROWS_PER_CHUNK;
    const int warp = threadIdx.x >> 5;
    const int lane = threadIdx.x & 31;

    __shared__ float acc[HH * MM];
    for (int i = threadIdx.x; i < HH * MM; i += blockDim.x)
        acc[i] = 0.0f;

    u64 ner2[HH][2], ar2[HH][2];
#pragma unroll
    for (int h = 0; h < HH; ++h) {
        const float4 e4 = __ldg((const float4*)(erase + (b * HH + h) * MM) + lane);
        const float4 a4 = __ldg((const float4*)(add   + (b * HH + h) * MM) + lane);
        ner2[h][0] = pack2(-e4.x, -e4.y);
        ner2[h][1] = pack2(-e4.z, -e4.w);
        ar2[h][0]  = pack2(a4.x, a4.y);
        ar2[h][1]  = pack2(a4.z, a4.w);
    }
    const u64 ones = pack2(1.0f, 1.0f);
    __syncthreads();

    u64 racc[HH][2];
#pragma unroll
    for (int h = 0; h < HH; ++h) { racc[h][0] = 0; racc[h][1] = 0; }

    const int iters = ROWS_PER_CHUNK / 8;  // 16
    for (int it = 0; it < iters; ++it) {
        const int s = s0 + it * 8 + warp;
        const ulonglong2 v = ((const ulonglong2*)(mem + ((size_t)b * SS + s) * MM))[lane];
        const float4 wq = __ldg(&g_w[b * SS + s]);   // broadcast, 1 line
        u64 w2[HH];
        w2[0] = pack2(wq.x, wq.x); w2[1] = pack2(wq.y, wq.y);
        w2[2] = pack2(wq.z, wq.z); w2[3] = pack2(wq.w, wq.w);

        u64 x0 = v.x, x1 = v.y;
#pragma unroll
        for (int h = 0; h < HH; ++h) {
            const u64 t0  = fma2(ner2[h][0], w2[h], ones);   // 1 - w*e
            const u64 t1  = fma2(ner2[h][1], w2[h], ones);
            const u64 wa0 = mul2(w2[h], ar2[h][0]);          // w*a
            const u64 wa1 = mul2(w2[h], ar2[h][1]);
            x0 = fma2(x0, t0, wa0);
            x1 = fma2(x1, t1, wa1);
        }
#pragma unroll
        for (int h = 0; h < HH; ++h) {
            racc[h][0] = fma2(w2[h], x0, racc[h][0]);
            racc[h][1] = fma2(w2[h], x1, racc[h][1]);
        }
    }

#pragma unroll
    for (int h = 0; h < HH; ++h) {
        const float2 r0 = unpack2(racc[h][0]);
        const float2 r1 = unpack2(racc[h][1]);
        atomicAdd(&acc[h * MM + lane * 4 + 0], r0.x);
        atomicAdd(&acc[h * MM + lane * 4 + 1], r0.y);
        atomicAdd(&acc[h * MM + lane * 4 + 2], r1.x);
        atomicAdd(&acc[h * MM + lane * 4 + 3], r1.y);
    }
    __syncthreads();

    for (int i = threadIdx.x; i < HH * MM; i += blockDim.x)
        atomicAdd(&out[b * HH * MM + i], acc[i]);
}

// ---------------------------------------------------------------------------
extern "C" void kernel_launch(void* const* d_in, const int* in_sizes, int n_in,
                              void* d_out, int out_size) {
    const float* mem   = (const float*)d_in[0];  // (B,S,M)
    const float* kq    = (const float*)d_in[1];  // (B,H,M)
    const float* beta  = (const float*)d_in[2];  // (B,H,1)
    const float* erase = (const float*)d_in[3];  // (B,H,M)
    const float* add   = (const float*)d_in[4];  // (B,H,M)
    float* out = (float*)d_out;                  // (B,H,M)

    (void)in_sizes; (void)n_in; (void)out_size;

    k1_dots<<<BB * 32, 256>>>(mem, kq, beta);
    k2_norm<<<BB * 8, 512>>>(out);
    k3_write_read<<<dim3(NCHUNK, BB), 256>>>(mem, erase, add, out);
}

// round 9
// speedup vs baseline: 1.3824x; 1.3824x over previous
#include <cuda_runtime.h>
#include <cuda_bf16.h>

#define BB 32
#define HH 4
#define SS 4096
#define MM 128

typedef unsigned long long u64;

__device__ __forceinline__ u64 fma2(u64 a, u64 b, u64 c) {
    u64 d; asm("fma.rn.f32x2 %0,%1,%2,%3;" : "=l"(d) : "l"(a), "l"(b), "l"(c)); return d;
}
__device__ __forceinline__ u64 mul2(u64 a, u64 b) {
    u64 d; asm("mul.rn.f32x2 %0,%1,%2;" : "=l"(d) : "l"(a), "l"(b)); return d;
}
__device__ __forceinline__ u64 pack2(float lo, float hi) {
    u64 r; asm("mov.b64 %0,{%1,%2};" : "=l"(r) : "f"(lo), "f"(hi)); return r;
}
__device__ __forceinline__ float2 unpack2(u64 x) {
    float2 f; asm("mov.b64 {%0,%1},%2;" : "=f"(f.x), "=f"(f.y) : "l"(x)); return f;
}
__device__ __forceinline__ float hadd2(u64 x) {
    const float2 f = unpack2(x); return f.x + f.y;
}

// Scratch
__device__ float4 g_w[BB * SS];    // scaled logits, then softmax weights
__device__ float4 g_pm[BB * 32];   // per-tile max (4 heads)
__device__ float4 g_ps[BB * 32];   // per-tile expsum (4 heads)

// ---------------------------------------------------------------------------
// Kernel 1: R4 structure (8 lanes/row, 4 rows/warp-quad, k in REGISTERS,
// depth-1 prefetch, 3-stage butterfly). Adds beta/knorm scaling and a cheap
// per-warp softmax-partial tail (1 barrier, no inner-loop LDS).
// ---------------------------------------------------------------------------
__global__ void __launch_bounds__(256, 2) k1_dots(const float* __restrict__ mem,
                                                  const float* __restrict__ kq,
                                                  const float* __restrict__ beta) {
    const int b    = blockIdx.x >> 5;        // 32 tiles per b
    const int tile = blockIdx.x & 31;        // 128 rows per tile
    const int tid  = threadIdx.x;
    const int warp = tid >> 5;
    const int lane = tid & 31;
    const int l8   = lane & 7;
    const int r    = lane >> 3;

    __shared__ float  scl[HH];
    __shared__ float4 wm8[8], ws8[8];

    // per-head scale = beta / max(||k_h||, eps)   (warps 0..3)
    if (warp < HH) {
        const float4 kv = ((const float4*)(kq + (b * HH + warp) * MM))[lane];
        float ss = kv.x * kv.x + kv.y * kv.y + kv.z * kv.z + kv.w * kv.w;
#pragma unroll
        for (int o = 16; o > 0; o >>= 1)
            ss += __shfl_xor_sync(0xFFFFFFFFu, ss, o);
        if (lane == 0)
            scl[warp] = beta[b * HH + warp] / fmaxf(sqrtf(ss), 1e-8f);
    }

    // k into registers: per lane, 4 heads x 4 float4 (cols j*32 + l8*4)
    ulonglong2 kk[HH][4];
#pragma unroll
    for (int h = 0; h < HH; ++h)
#pragma unroll
        for (int j = 0; j < 4; ++j)
            kk[h][j] = *(const ulonglong2*)(kq + ((b * HH + h) << 7) + j * 32 + l8 * 4);

    __syncthreads();
    const float4 sc = make_float4(scl[0], scl[1], scl[2], scl[3]);

    // rows: s = tile*128 + warp*4 + r + q*32, q = 0..3
    const int srow0 = tile * 128 + warp * 4 + r;
    const float* base = mem + ((size_t)b * SS + srow0) * MM + l8 * 4;

    ulonglong2 vn[4];
#pragma unroll
    for (int j = 0; j < 4; ++j)
        vn[j] = *(const ulonglong2*)(base + j * 32);

    float4 lg[4];

#pragma unroll
    for (int q = 0; q < 4; ++q) {
        ulonglong2 vc[4];
#pragma unroll
        for (int j = 0; j < 4; ++j) vc[j] = vn[j];
        if (q < 3) {
            const float* nb = base + (size_t)(q + 1) * 32 * MM;
#pragma unroll
            for (int j = 0; j < 4; ++j)
                vn[j] = *(const ulonglong2*)(nb + j * 32);
        }

        u64 ss2 = 0, d2[HH] = {0, 0, 0, 0};
#pragma unroll
        for (int j = 0; j < 4; ++j) {
            ss2 = fma2(vc[j].x, vc[j].x, ss2);
            ss2 = fma2(vc[j].y, vc[j].y, ss2);
#pragma unroll
            for (int h = 0; h < HH; ++h) {
                d2[h] = fma2(vc[j].x, kk[h][j].x, d2[h]);
                d2[h] = fma2(vc[j].y, kk[h][j].y, d2[h]);
            }
        }

        float ssum = hadd2(ss2);
        float sd[HH];
#pragma unroll
        for (int h = 0; h < HH; ++h) sd[h] = hadd2(d2[h]);

#pragma unroll
        for (int o = 4; o > 0; o >>= 1) {
            ssum += __shfl_xor_sync(0xFFFFFFFFu, ssum, o);
#pragma unroll
            for (int h = 0; h < HH; ++h)
                sd[h] += __shfl_xor_sync(0xFFFFFFFFu, sd[h], o);
        }

        const float rmn = 1.0f / fmaxf(sqrtf(ssum), 1e-8f);
        lg[q] = make_float4(sd[0] * rmn * sc.x, sd[1] * rmn * sc.y,
                            sd[2] * rmn * sc.z, sd[3] * rmn * sc.w);
        if (l8 == 0)
            g_w[b * SS + srow0 + q * 32] = lg[q];
    }

    // ---- cheap softmax partials: per-warp butterfly, 1 block barrier ----
    // every lane holds valid logits for its row (butterfly was an allreduce)
    float4 mx = lg[0];
#pragma unroll
    for (int q = 1; q < 4; ++q) {
        mx.x = fmaxf(mx.x, lg[q].x); mx.y = fmaxf(mx.y, lg[q].y);
        mx.z = fmaxf(mx.z, lg[q].z); mx.w = fmaxf(mx.w, lg[q].w);
    }
#pragma unroll
    for (int o = 16; o > 0; o >>= 1) {
        mx.x = fmaxf(mx.x, __shfl_xor_sync(0xFFFFFFFFu, mx.x, o));
        mx.y = fmaxf(mx.y, __shfl_xor_sync(0xFFFFFFFFu, mx.y, o));
        mx.z = fmaxf(mx.z, __shfl_xor_sync(0xFFFFFFFFu, mx.z, o));
        mx.w = fmaxf(mx.w, __shfl_xor_sync(0xFFFFFFFFu, mx.w, o));
    }
    // expsum: only l8==0 lanes contribute (each row counted once)
    float4 es = make_float4(0, 0, 0, 0);
    if (l8 == 0) {
#pragma unroll
        for (int q = 0; q < 4; ++q) {
            es.x += __expf(lg[q].x - mx.x);
            es.y += __expf(lg[q].y - mx.y);
            es.z += __expf(lg[q].z - mx.z);
            es.w += __expf(lg[q].w - mx.w);
        }
    }
#pragma unroll
    for (int o = 16; o > 0; o >>= 1) {
        es.x += __shfl_xor_sync(0xFFFFFFFFu, es.x, o);
        es.y += __shfl_xor_sync(0xFFFFFFFFu, es.y, o);
        es.z += __shfl_xor_sync(0xFFFFFFFFu, es.z, o);
        es.w += __shfl_xor_sync(0xFFFFFFFFu, es.w, o);
    }
    if (lane == 0) { wm8[warp] = mx; ws8[warp] = es; }
    __syncthreads();

    if (warp == 0) {
        float4 m = (lane < 8) ? wm8[lane]
                              : make_float4(-1e30f, -1e30f, -1e30f, -1e30f);
        float4 mw = m;
#pragma unroll
        for (int o = 4; o > 0; o >>= 1) {
            m.x = fmaxf(m.x, __shfl_xor_sync(0xFFFFFFFFu, m.x, o));
            m.y = fmaxf(m.y, __shfl_xor_sync(0xFFFFFFFFu, m.y, o));
            m.z = fmaxf(m.z, __shfl_xor_sync(0xFFFFFFFFu, m.z, o));
            m.w = fmaxf(m.w, __shfl_xor_sync(0xFFFFFFFFu, m.w, o));
        }
        float4 s = make_float4(0, 0, 0, 0);
        if (lane < 8) {
            const float4 sw = ws8[lane];
            s.x = sw.x * __expf(mw.x - m.x);
            s.y = sw.y * __expf(mw.y - m.y);
            s.z = sw.z * __expf(mw.z - m.z);
            s.w = sw.w * __expf(mw.w - m.w);
        }
#pragma unroll
        for (int o = 4; o > 0; o >>= 1) {
            s.x += __shfl_xor_sync(0xFFFFFFFFu, s.x, o);
            s.y += __shfl_xor_sync(0xFFFFFFFFu, s.y, o);
            s.z += __shfl_xor_sync(0xFFFFFFFFu, s.z, o);
            s.w += __shfl_xor_sync(0xFFFFFFFFu, s.w, o);
        }
        if (lane == 0) {
            g_pm[b * 32 + tile] = m;
            g_ps[b * 32 + tile] = s;
        }
    }
}

// ---------------------------------------------------------------------------
// Kernel 2: normalize. grid 256 (8 chunks x 32 b), 512 threads.
// Combines 32 tile partials, then w = exp(logit - m*) / S. Zeroes out.
// ---------------------------------------------------------------------------
__global__ void __launch_bounds__(512) k2_norm(float* __restrict__ out) {
    const int b     = blockIdx.x >> 3;
    const int chunk = blockIdx.x & 7;
    const int tid   = threadIdx.x;

    __shared__ float4 sm_m, sm_is;

    if (tid < 32) {
        float4 m4 = g_pm[b * 32 + tid];
        float4 s4 = g_ps[b * 32 + tid];
        float4 m = m4;
#pragma unroll
        for (int o = 16; o > 0; o >>= 1) {
            m.x = fmaxf(m.x, __shfl_xor_sync(0xFFFFFFFFu, m.x, o));
            m.y = fmaxf(m.y, __shfl_xor_sync(0xFFFFFFFFu, m.y, o));
            m.z = fmaxf(m.z, __shfl_xor_sync(0xFFFFFFFFu, m.z, o));
            m.w = fmaxf(m.w, __shfl_xor_sync(0xFFFFFFFFu, m.w, o));
        }
        float4 s;
        s.x = s4.x * __expf(m4.x - m.x);
        s.y = s4.y * __expf(m4.y - m.y);
        s.z = s4.z * __expf(m4.z - m.z);
        s.w = s4.w * __expf(m4.w - m.w);
#pragma unroll
        for (int o = 16; o > 0; o >>= 1) {
            s.x += __shfl_xor_sync(0xFFFFFFFFu, s.x, o);
            s.y += __shfl_xor_sync(0xFFFFFFFFu, s.y, o);
            s.z += __shfl_xor_sync(0xFFFFFFFFu, s.z, o);
            s.w += __shfl_xor_sync(0xFFFFFFFFu, s.w, o);
        }
        if (tid == 0) {
            sm_m  = m;
            sm_is = make_float4(1.0f / s.x, 1.0f / s.y, 1.0f / s.z, 1.0f / s.w);
        }
    }
    __syncthreads();

    const float4 m  = sm_m;
    const float4 is = sm_is;
    const int idx = b * SS + chunk * 512 + tid;
    float4 lg = g_w[idx];
    lg.x = __expf(lg.x - m.x) * is.x;
    lg.y = __expf(lg.y - m.y) * is.y;
    lg.z = __expf(lg.z - m.z) * is.z;
    lg.w = __expf(lg.w - m.w) * is.w;
    g_w[idx] = lg;

    if (chunk == 0)
        out[b * HH * MM + tid] = 0.0f;
}

// ---------------------------------------------------------------------------
// Kernel 3: fused write + read (R4 structure) + depth-2 prefetch, no occ cap.
// ---------------------------------------------------------------------------
#define NCHUNK 32
#define ROWS_PER_CHUNK (SS / NCHUNK)   // 128
#define K3_ITERS (ROWS_PER_CHUNK / 8)  // 16

__global__ void __launch_bounds__(256) k3_write_read(const float* __restrict__ mem,
                                                     const float* __restrict__ erase,
                                                     const float* __restrict__ add,
                                                     float* __restrict__ out) {
    const int b  = blockIdx.y;
    const int s0 = blockIdx.x * ROWS_PER_CHUNK;
    const int warp = threadIdx.x >> 5;
    const int lane = threadIdx.x & 31;

    __shared__ float acc[HH * MM];
    for (int i = threadIdx.x; i < HH * MM; i += blockDim.x)
        acc[i] = 0.0f;

    u64 ner2[HH][2], ar2[HH][2];
#pragma unroll
    for (int h = 0; h < HH; ++h) {
        const float4 e4 = __ldg((const float4*)(erase + (b * HH + h) * MM) + lane);
        const float4 a4 = __ldg((const float4*)(add   + (b * HH + h) * MM) + lane);
        ner2[h][0] = pack2(-e4.x, -e4.y);
        ner2[h][1] = pack2(-e4.z, -e4.w);
        ar2[h][0]  = pack2(a4.x, a4.y);
        ar2[h][1]  = pack2(a4.z, a4.w);
    }
    const u64 ones = pack2(1.0f, 1.0f);
    __syncthreads();

    u64 racc[HH][2];
#pragma unroll
    for (int h = 0; h < HH; ++h) { racc[h][0] = 0; racc[h][1] = 0; }

    const ulonglong2* vbase =
        (const ulonglong2*)(mem + ((size_t)b * SS + s0 + warp) * MM) + lane;
    const float4* wbase = &g_w[b * SS + s0 + warp];

    ulonglong2 vbuf[2];
    float4 wbuf[2];
    vbuf[0] = vbase[0];        wbuf[0] = __ldg(wbase);
    vbuf[1] = vbase[8 * 32];   wbuf[1] = __ldg(wbase + 8);

#pragma unroll
    for (int it = 0; it < K3_ITERS; ++it) {
        const ulonglong2 v = vbuf[it & 1];
        const float4 wq = wbuf[it & 1];
        if (it < K3_ITERS - 2) {
            vbuf[it & 1] = vbase[(size_t)(it + 2) * 8 * 32];
            wbuf[it & 1] = __ldg(wbase + (it + 2) * 8);
        }

        u64 w2[HH];
        w2[0] = pack2(wq.x, wq.x); w2[1] = pack2(wq.y, wq.y);
        w2[2] = pack2(wq.z, wq.z); w2[3] = pack2(wq.w, wq.w);

        u64 x0 = v.x, x1 = v.y;
#pragma unroll
        for (int h = 0; h < HH; ++h) {
            const u64 t0  = fma2(ner2[h][0], w2[h], ones);   // 1 - w*e
            const u64 t1  = fma2(ner2[h][1], w2[h], ones);
            const u64 wa0 = mul2(w2[h], ar2[h][0]);          // w*a
            const u64 wa1 = mul2(w2[h], ar2[h][1]);
            x0 = fma2(x0, t0, wa0);
            x1 = fma2(x1, t1, wa1);
        }
#pragma unroll
        for (int h = 0; h < HH; ++h) {
            racc[h][0] = fma2(w2[h], x0, racc[h][0]);
            racc[h][1] = fma2(w2[h], x1, racc[h][1]);
        }
    }

#pragma unroll
    for (int h = 0; h < HH; ++h) {
        const float2 r0 = unpack2(racc[h][0]);
        const float2 r1 = unpack2(racc[h][1]);
        atomicAdd(&acc[h * MM + lane * 4 + 0], r0.x);
        atomicAdd(&acc[h * MM + lane * 4 + 1], r0.y);
        atomicAdd(&acc[h * MM + lane * 4 + 2], r1.x);
        atomicAdd(&acc[h * MM + lane * 4 + 3], r1.y);
    }
    __syncthreads();

    for (int i = threadIdx.x; i < HH * MM; i += blockDim.x)
        atomicAdd(&out[b * HH * MM + i], acc[i]);
}

// ---------------------------------------------------------------------------
extern "C" void kernel_launch(void* const* d_in, const int* in_sizes, int n_in,
                              void* d_out, int out_size) {
    const float* mem   = (const float*)d_in[0];  // (B,S,M)
    const float* kq    = (const float*)d_in[1];  // (B,H,M)
    const float* beta  = (const float*)d_in[2];  // (B,H,1)
    const float* erase = (const float*)d_in[3];  // (B,H,M)
    const float* add   = (const float*)d_in[4];  // (B,H,M)
    float* out = (float*)d_out;                  // (B,H,M)

    (void)in_sizes; (void)n_in; (void)out_size;

    k1_dots<<<BB * 32, 256>>>(mem, kq, beta);
    k2_norm<<<BB * 8, 512>>>(out);
    k3_write_read<<<dim3(NCHUNK, BB), 256>>>(mem, erase, add, out);
}

// round 10
// speedup vs baseline: 1.5260x; 1.1039x over previous
#include <cuda_runtime.h>
#include <cuda_bf16.h>
#include <cstdint>

#define BB 32
#define HH 4
#define SS 4096
#define MM 128

typedef unsigned long long u64;

__device__ __forceinline__ u64 fma2(u64 a, u64 b, u64 c) {
    u64 d; asm("fma.rn.f32x2 %0,%1,%2,%3;" : "=l"(d) : "l"(a), "l"(b), "l"(c)); return d;
}
__device__ __forceinline__ u64 mul2(u64 a, u64 b) {
    u64 d; asm("mul.rn.f32x2 %0,%1,%2;" : "=l"(d) : "l"(a), "l"(b)); return d;
}
__device__ __forceinline__ u64 pack2(float lo, float hi) {
    u64 r; asm("mov.b64 %0,{%1,%2};" : "=l"(r) : "f"(lo), "f"(hi)); return r;
}
__device__ __forceinline__ float2 unpack2(u64 x) {
    float2 f; asm("mov.b64 {%0,%1},%2;" : "=f"(f.x), "=f"(f.y) : "l"(x)); return f;
}
__device__ __forceinline__ float hadd2(u64 x) {
    const float2 f = unpack2(x); return f.x + f.y;
}
__device__ __forceinline__ uint32_t smem_u32(const void* p) {
    return (uint32_t)__cvta_generic_to_shared(p);
}

#define CP_ASYNC16(dst, src) \
    asm volatile("cp.async.cg.shared.global [%0], [%1], 16;" :: "r"(dst), "l"(src))
#define CP_COMMIT() asm volatile("cp.async.commit_group;")
#define CP_WAIT(n)  asm volatile("cp.async.wait_group %0;" :: "n"(n))

// Scratch
__device__ float4 g_w[BB * SS];    // scaled logits, then softmax weights
__device__ float4 g_pm[BB * 16];   // per-tile(256-row) max (4 heads)
__device__ float4 g_ps[BB * 16];   // per-tile expsum (4 heads)

// ---------------------------------------------------------------------------
// Kernel 1: cp.async 4-stage pipeline (32-row / 16KB stages), 256-row tile.
// Compute: 8 lanes/row from SMEM, k in registers, 3-stage butterfly,
// online softmax partials per block.
// ---------------------------------------------------------------------------
#define K1_TILE 256
#define K1_STGB 16384                 // stage bytes (32 rows * 512B)

__global__ void __launch_bounds__(256, 2) k1_dots(const float* __restrict__ mem,
                                                  const float* __restrict__ kq,
                                                  const float* __restrict__ beta) {
    extern __shared__ float stg[];           // 4 * 4096 floats
    __shared__ float  scl[HH];
    __shared__ float4 wm8[8], ws8[8];

    const int b    = blockIdx.x >> 4;        // 16 tiles per b
    const int tile = blockIdx.x & 15;
    const int tid  = threadIdx.x;
    const int warp = tid >> 5;
    const int lane = tid & 31;
    const int l8   = lane & 7;
    const int r    = lane >> 3;

    const int srow0 = tile * K1_TILE;
    const char* gbase = (const char*)(mem + ((size_t)b * SS + srow0) * MM);
    const uint32_t sbase = smem_u32(stg);

    // prologue: issue stages 0..2
#pragma unroll
    for (int p = 0; p < 3; ++p) {
        const char* g = gbase + (size_t)p * K1_STGB + (size_t)tid * 16;
        const uint32_t d = sbase + p * K1_STGB + tid * 16;
#pragma unroll
        for (int c = 0; c < 4; ++c)
            CP_ASYNC16(d + c * 4096, g + c * 4096);
        CP_COMMIT();
    }

    // per-head scale = beta / max(||k_h||, eps)
    if (warp < HH) {
        const float4 kv = ((const float4*)(kq + (b * HH + warp) * MM))[lane];
        float ss = kv.x * kv.x + kv.y * kv.y + kv.z * kv.z + kv.w * kv.w;
#pragma unroll
        for (int o = 16; o > 0; o >>= 1)
            ss += __shfl_xor_sync(0xFFFFFFFFu, ss, o);
        if (lane == 0)
            scl[warp] = beta[b * HH + warp] / fmaxf(sqrtf(ss), 1e-8f);
    }

    // k into registers
    ulonglong2 kk[HH][4];
#pragma unroll
    for (int h = 0; h < HH; ++h)
#pragma unroll
        for (int j = 0; j < 4; ++j)
            kk[h][j] = *(const ulonglong2*)(kq + ((b * HH + h) << 7) + j * 32 + l8 * 4);

    __syncthreads();
    const float4 sc = make_float4(scl[0], scl[1], scl[2], scl[3]);

    float4 runm = make_float4(-1e30f, -1e30f, -1e30f, -1e30f);
    float4 runs = make_float4(0, 0, 0, 0);

#pragma unroll
    for (int i = 0; i < 8; ++i) {
        if (i <= 5)      CP_WAIT(2);
        else if (i == 6) CP_WAIT(1);
        else             CP_WAIT(0);
        __syncthreads();

        const float* sp = stg + (i & 3) * 4096 + (warp * 4 + r) * 128 + l8 * 4;

        u64 ss2 = 0, d2[HH] = {0, 0, 0, 0};
#pragma unroll
        for (int j = 0; j < 4; ++j) {
            const ulonglong2 v = *(const ulonglong2*)(sp + j * 32);
            ss2 = fma2(v.x, v.x, ss2);
            ss2 = fma2(v.y, v.y, ss2);
#pragma unroll
            for (int h = 0; h < HH; ++h) {
                d2[h] = fma2(v.x, kk[h][j].x, d2[h]);
                d2[h] = fma2(v.y, kk[h][j].y, d2[h]);
            }
        }

        float ssum = hadd2(ss2);
        float sd[HH];
#pragma unroll
        for (int h = 0; h < HH; ++h) sd[h] = hadd2(d2[h]);
#pragma unroll
        for (int o = 4; o > 0; o >>= 1) {
            ssum += __shfl_xor_sync(0xFFFFFFFFu, ssum, o);
#pragma unroll
            for (int h = 0; h < HH; ++h)
                sd[h] += __shfl_xor_sync(0xFFFFFFFFu, sd[h], o);
        }

        const float rmn = 1.0f / fmaxf(sqrtf(ssum), 1e-8f);
        const float4 lg = make_float4(sd[0] * rmn * sc.x, sd[1] * rmn * sc.y,
                                      sd[2] * rmn * sc.z, sd[3] * rmn * sc.w);
        const int s = srow0 + i * 32 + warp * 4 + r;
        if (l8 == 0)
            g_w[b * SS + s] = lg;

        // online softmax partial update (rows counted once via l8==0)
        float4 nm;
        nm.x = fmaxf(runm.x, lg.x); nm.y = fmaxf(runm.y, lg.y);
        nm.z = fmaxf(runm.z, lg.z); nm.w = fmaxf(runm.w, lg.w);
        const float g = (l8 == 0) ? 1.0f : 0.0f;
        runs.x = runs.x * __expf(runm.x - nm.x) + g * __expf(lg.x - nm.x);
        runs.y = runs.y * __expf(runm.y - nm.y) + g * __expf(lg.y - nm.y);
        runs.z = runs.z * __expf(runm.z - nm.z) + g * __expf(lg.z - nm.z);
        runs.w = runs.w * __expf(runm.w - nm.w) + g * __expf(lg.w - nm.w);
        runm = nm;

        if (i < 5) {
            const int p = i + 3;
            const char* gg = gbase + (size_t)p * K1_STGB + (size_t)tid * 16;
            const uint32_t d = sbase + (p & 3) * K1_STGB + tid * 16;
#pragma unroll
            for (int c = 0; c < 4; ++c)
                CP_ASYNC16(d + c * 4096, gg + c * 4096);
            CP_COMMIT();
        }
    }

    // combine (m,s) across 32 lanes (lanes with s=0 are harmless)
#pragma unroll
    for (int o = 16; o > 0; o >>= 1) {
        float4 om, os;
        om.x = __shfl_xor_sync(0xFFFFFFFFu, runm.x, o);
        om.y = __shfl_xor_sync(0xFFFFFFFFu, runm.y, o);
        om.z = __shfl_xor_sync(0xFFFFFFFFu, runm.z, o);
        om.w = __shfl_xor_sync(0xFFFFFFFFu, runm.w, o);
        os.x = __shfl_xor_sync(0xFFFFFFFFu, runs.x, o);
        os.y = __shfl_xor_sync(0xFFFFFFFFu, runs.y, o);
        os.z = __shfl_xor_sync(0xFFFFFFFFu, runs.z, o);
        os.w = __shfl_xor_sync(0xFFFFFFFFu, runs.w, o);
        float4 nm;
        nm.x = fmaxf(runm.x, om.x); nm.y = fmaxf(runm.y, om.y);
        nm.z = fmaxf(runm.z, om.z); nm.w = fmaxf(runm.w, om.w);
        runs.x = runs.x * __expf(runm.x - nm.x) + os.x * __expf(om.x - nm.x);
        runs.y = runs.y * __expf(runm.y - nm.y) + os.y * __expf(om.y - nm.y);
        runs.z = runs.z * __expf(runm.z - nm.z) + os.z * __expf(om.z - nm.z);
        runs.w = runs.w * __expf(runm.w - nm.w) + os.w * __expf(om.w - nm.w);
        runm = nm;
    }
    if (lane == 0) { wm8[warp] = runm; ws8[warp] = runs; }
    __syncthreads();

    if (warp == 0 && lane < 8) {
        float4 m = wm8[lane], s = ws8[lane];
#pragma unroll
        for (int o = 4; o > 0; o >>= 1) {
            float4 om, os;
            om.x = __shfl_xor_sync(0xFFFFFFFFu, m.x, o);
            om.y = __shfl_xor_sync(0xFFFFFFFFu, m.y, o);
            om.z = __shfl_xor_sync(0xFFFFFFFFu, m.z, o);
            om.w = __shfl_xor_sync(0xFFFFFFFFu, m.w, o);
            os.x = __shfl_xor_sync(0xFFFFFFFFu, s.x, o);
            os.y = __shfl_xor_sync(0xFFFFFFFFu, s.y, o);
            os.z = __shfl_xor_sync(0xFFFFFFFFu, s.z, o);
            os.w = __shfl_xor_sync(0xFFFFFFFFu, s.w, o);
            float4 nm;
            nm.x = fmaxf(m.x, om.x); nm.y = fmaxf(m.y, om.y);
            nm.z = fmaxf(m.z, om.z); nm.w = fmaxf(m.w, om.w);
            s.x = s.x * __expf(m.x - nm.x) + os.x * __expf(om.x - nm.x);
            s.y = s.y * __expf(m.y - nm.y) + os.y * __expf(om.y - nm.y);
            s.z = s.z * __expf(m.z - nm.z) + os.z * __expf(om.z - nm.z);
            s.w = s.w * __expf(m.w - nm.w) + os.w * __expf(om.w - nm.w);
            m = nm;
        }
        if (lane == 0) {
            g_pm[b * 16 + tile] = m;
            g_ps[b * 16 + tile] = s;
        }
    }
}

// ---------------------------------------------------------------------------
// Kernel 2: normalize. grid 256 (8 chunks x 32 b), 512 threads.
// Combines 16 tile partials, then w = exp(logit - m*) / S. Zeroes out.
// ---------------------------------------------------------------------------
__global__ void __launch_bounds__(512) k2_norm(float* __restrict__ out) {
    const int b     = blockIdx.x >> 3;
    const int chunk = blockIdx.x & 7;
    const int tid   = threadIdx.x;

    __shared__ float4 sm_m, sm_is;

    if (tid < 32) {
        const bool val = tid < 16;
        float4 m4 = val ? g_pm[b * 16 + tid]
                        : make_float4(-1e30f, -1e30f, -1e30f, -1e30f);
        float4 s4 = val ? g_ps[b * 16 + tid] : make_float4(0, 0, 0, 0);
        float4 m = m4;
#pragma unroll
        for (int o = 16; o > 0; o >>= 1) {
            m.x = fmaxf(m.x, __shfl_xor_sync(0xFFFFFFFFu, m.x, o));
            m.y = fmaxf(m.y, __shfl_xor_sync(0xFFFFFFFFu, m.y, o));
            m.z = fmaxf(m.z, __shfl_xor_sync(0xFFFFFFFFu, m.z, o));
            m.w = fmaxf(m.w, __shfl_xor_sync(0xFFFFFFFFu, m.w, o));
        }
        float4 s;
        s.x = s4.x * __expf(m4.x - m.x);
        s.y = s4.y * __expf(m4.y - m.y);
        s.z = s4.z * __expf(m4.z - m.z);
        s.w = s4.w * __expf(m4.w - m.w);
#pragma unroll
        for (int o = 16; o > 0; o >>= 1) {
            s.x += __shfl_xor_sync(0xFFFFFFFFu, s.x, o);
            s.y += __shfl_xor_sync(0xFFFFFFFFu, s.y, o);
            s.z += __shfl_xor_sync(0xFFFFFFFFu, s.z, o);
            s.w += __shfl_xor_sync(0xFFFFFFFFu, s.w, o);
        }
        if (tid == 0) {
            sm_m  = m;
            sm_is = make_float4(1.0f / s.x, 1.0f / s.y, 1.0f / s.z, 1.0f / s.w);
        }
    }
    __syncthreads();

    const float4 m  = sm_m;
    const float4 is = sm_is;
    const int idx = b * SS + chunk * 512 + tid;
    float4 lg = g_w[idx];
    lg.x = __expf(lg.x - m.x) * is.x;
    lg.y = __expf(lg.y - m.y) * is.y;
    lg.z = __expf(lg.z - m.z) * is.z;
    lg.w = __expf(lg.w - m.w) * is.w;
    g_w[idx] = lg;

    if (chunk == 0)
        out[b * HH * MM + tid] = 0.0f;
}

// ---------------------------------------------------------------------------
// Kernel 3: fused write + read, cp.async 4-stage pipeline; mem rows AND
// w float4s staged; math unchanged (proven).
// ---------------------------------------------------------------------------
#define K3_TILE 256
#define K3_STRF 4224                  // stage stride in floats (4096 mem + 128 w)
#define K3_WOFF 4096                  // float offset of w area within stage

__global__ void __launch_bounds__(256, 3) k3_write_read(const float* __restrict__ mem,
                                                        const float* __restrict__ erase,
                                                        const float* __restrict__ add,
                                                        float* __restrict__ out) {
    extern __shared__ float stg[];           // 4 * K3_STRF floats
    __shared__ float acc[HH * MM];

    const int b    = blockIdx.y;
    const int tile = blockIdx.x;             // 16 tiles per b
    const int tid  = threadIdx.x;
    const int warp = tid >> 5;
    const int lane = tid & 31;

    const int srow0 = tile * K3_TILE;
    const char* gbase = (const char*)(mem + ((size_t)b * SS + srow0) * MM);
    const char* wgbase = (const char*)(&g_w[b * SS + srow0]);
    const uint32_t sbase = smem_u32(stg);

    // prologue: issue stages 0..2
#pragma unroll
    for (int p = 0; p < 3; ++p) {
        const char* g = gbase + (size_t)p * 16384 + (size_t)tid * 16;
        const uint32_t d = sbase + p * (K3_STRF * 4) + tid * 16;
#pragma unroll
        for (int c = 0; c < 4; ++c)
            CP_ASYNC16(d + c * 4096, g + c * 4096);
        if (tid < 32)
            CP_ASYNC16(sbase + p * (K3_STRF * 4) + K3_WOFF * 4 + tid * 16,
                       wgbase + (size_t)p * 512 + (size_t)tid * 16);
        CP_COMMIT();
    }

    for (int i = tid; i < HH * MM; i += 256)
        acc[i] = 0.0f;

    u64 ner2[HH][2], ar2[HH][2];
#pragma unroll
    for (int h = 0; h < HH; ++h) {
        const float4 e4 = __ldg((const float4*)(erase + (b * HH + h) * MM) + lane);
        const float4 a4 = __ldg((const float4*)(add   + (b * HH + h) * MM) + lane);
        ner2[h][0] = pack2(-e4.x, -e4.y);
        ner2[h][1] = pack2(-e4.z, -e4.w);
        ar2[h][0]  = pack2(a4.x, a4.y);
        ar2[h][1]  = pack2(a4.z, a4.w);
    }
    const u64 ones = pack2(1.0f, 1.0f);

    u64 racc[HH][2];
#pragma unroll
    for (int h = 0; h < HH; ++h) { racc[h][0] = 0; racc[h][1] = 0; }

#pragma unroll
    for (int i = 0; i < 8; ++i) {
        if (i <= 5)      CP_WAIT(2);
        else if (i == 6) CP_WAIT(1);
        else             CP_WAIT(0);
        __syncthreads();

        const float* sp = stg + (i & 3) * K3_STRF;
#pragma unroll
        for (int q = 0; q < 4; ++q) {
            const int rl = warp * 4 + q;
            const ulonglong2 v = *(const ulonglong2*)(sp + rl * 128 + lane * 4);
            const float4 wq = *(const float4*)(sp + K3_WOFF + rl * 4);

            u64 w2[HH];
            w2[0] = pack2(wq.x, wq.x); w2[1] = pack2(wq.y, wq.y);
            w2[2] = pack2(wq.z, wq.z); w2[3] = pack2(wq.w, wq.w);

            u64 x0 = v.x, x1 = v.y;
#pragma unroll
            for (int h = 0; h < HH; ++h) {
                const u64 t0  = fma2(ner2[h][0], w2[h], ones);   // 1 - w*e
                const u64 t1  = fma2(ner2[h][1], w2[h], ones);
                const u64 wa0 = mul2(w2[h], ar2[h][0]);          // w*a
                const u64 wa1 = mul2(w2[h], ar2[h][1]);
                x0 = fma2(x0, t0, wa0);
                x1 = fma2(x1, t1, wa1);
            }
#pragma unroll
            for (int h = 0; h < HH; ++h) {
                racc[h][0] = fma2(w2[h], x0, racc[h][0]);
                racc[h][1] = fma2(w2[h], x1, racc[h][1]);
            }
        }

        if (i < 5) {
            const int p = i + 3;
            const char* g = gbase + (size_t)p * 16384 + (size_t)tid * 16;
            const uint32_t d = sbase + (p & 3) * (K3_STRF * 4) + tid * 16;
#pragma unroll
            for (int c = 0; c < 4; ++c)
                CP_ASYNC16(d + c * 4096, g + c * 4096);
            if (tid < 32)
                CP_ASYNC16(sbase + (p & 3) * (K3_STRF * 4) + K3_WOFF * 4 + tid * 16,
                           wgbase + (size_t)p * 512 + (size_t)tid * 16);
            CP_COMMIT();
        }
        __syncthreads();
    }

#pragma unroll
    for (int h = 0; h < HH; ++h) {
        const float2 r0 = unpack2(racc[h][0]);
        const float2 r1 = unpack2(racc[h][1]);
        atomicAdd(&acc[h * MM + lane * 4 + 0], r0.x);
        atomicAdd(&acc[h * MM + lane * 4 + 1], r0.y);
        atomicAdd(&acc[h * MM + lane * 4 + 2], r1.x);
        atomicAdd(&acc[h * MM + lane * 4 + 3], r1.y);
    }
    __syncthreads();

    for (int i = tid; i < HH * MM; i += 256)
        atomicAdd(&out[b * HH * MM + i], acc[i]);
}

// ---------------------------------------------------------------------------
extern "C" void kernel_launch(void* const* d_in, const int* in_sizes, int n_in,
                              void* d_out, int out_size) {
    const float* mem   = (const float*)d_in[0];  // (B,S,M)
    const float* kq    = (const float*)d_in[1];  // (B,H,M)
    const float* beta  = (const float*)d_in[2];  // (B,H,1)
    const float* erase = (const float*)d_in[3];  // (B,H,M)
    const float* add   = (const float*)d_in[4];  // (B,H,M)
    float* out = (float*)d_out;                  // (B,H,M)

    (void)in_sizes; (void)n_in; (void)out_size;

    static bool attr_done = false;
    if (!attr_done) {
        cudaFuncSetAttribute(k1_dots, cudaFuncAttributeMaxDynamicSharedMemorySize,
                             4 * K1_STGB);
        cudaFuncSetAttribute(k3_write_read, cudaFuncAttributeMaxDynamicSharedMemorySize,
                             4 * K3_STRF * 4);
        attr_done = true;
    }

    k1_dots<<<BB * 16, 256, 4 * K1_STGB>>>(mem, kq, beta);
    k2_norm<<<BB * 8, 512>>>(out);
    k3_write_read<<<dim3(16, BB), 256, 4 * K3_STRF * 4>>>(mem, erase, add, out);
}

// round 12
// speedup vs baseline: 1.5973x; 1.0467x over previous
#include <cuda_runtime.h>
#include <cuda_bf16.h>
#include <cstdint>

#define BB 32
#define HH 4
#define SS 4096
#define MM 128

typedef unsigned long long u64;

__device__ __forceinline__ u64 fma2(u64 a, u64 b, u64 c) {
    u64 d; asm("fma.rn.f32x2 %0,%1,%2,%3;" : "=l"(d) : "l"(a), "l"(b), "l"(c)); return d;
}
__device__ __forceinline__ u64 mul2(u64 a, u64 b) {
    u64 d; asm("mul.rn.f32x2 %0,%1,%2;" : "=l"(d) : "l"(a), "l"(b)); return d;
}
__device__ __forceinline__ u64 pack2(float lo, float hi) {
    u64 r; asm("mov.b64 %0,{%1,%2};" : "=l"(r) : "f"(lo), "f"(hi)); return r;
}
__device__ __forceinline__ float2 unpack2(u64 x) {
    float2 f; asm("mov.b64 {%0,%1},%2;" : "=f"(f.x), "=f"(f.y) : "l"(x)); return f;
}
__device__ __forceinline__ float hadd2(u64 x) {
    const float2 f = unpack2(x); return f.x + f.y;
}
__device__ __forceinline__ uint32_t smem_u32(const void* p) {
    return (uint32_t)__cvta_generic_to_shared(p);
}

#define CP_ASYNC16(dst, src) \
    asm volatile("cp.async.cg.shared.global [%0], [%1], 16;" :: "r"(dst), "l"(src))
#define CP_COMMIT() asm volatile("cp.async.commit_group;")
#define CP_WAIT(n)  asm volatile("cp.async.wait_group %0;" :: "n"(n))

// Scratch
__device__ float4 g_w[BB * SS];    // scaled logits, then softmax weights
__device__ float4 g_ps[BB * 16];   // per-tile(256-row) expsum (4 heads)

// ---------------------------------------------------------------------------
// Kernel 1: cp.async 6-stage ring (32-row / 16KB stages), 256-row tile.
// Logits are bounded (|cossim|<=1, beta in [0,1)) => softmax WITHOUT max:
// only expsum partials needed. 8 lanes/row, k in registers, 3-stage butterfly.
// ---------------------------------------------------------------------------
#define K1_TILE 256
#define K1_STGB 16384                 // stage bytes (32 rows * 512B)
#define K1_RING 6

__global__ void __launch_bounds__(256, 2) k1_dots(const float* __restrict__ mem,
                                                  const float* __restrict__ kq,
                                                  const float* __restrict__ beta) {
    extern __shared__ float stg[];           // K1_RING * 4096 floats
    __shared__ float  scl[HH];
    __shared__ float4 ws8[8];

    const int b    = blockIdx.x >> 4;        // 16 tiles per b
    const int tile = blockIdx.x & 15;
    const int tid  = threadIdx.x;
    const int warp = tid >> 5;
    const int lane = tid & 31;
    const int l8   = lane & 7;
    const int r    = lane >> 3;

    const int srow0 = tile * K1_TILE;
    const char* gbase = (const char*)(mem + ((size_t)b * SS + srow0) * MM);
    const uint32_t sbase = smem_u32(stg);

    // prologue: issue stages 0..4
#pragma unroll
    for (int p = 0; p < 5; ++p) {
        const char* g = gbase + (size_t)p * K1_STGB + (size_t)tid * 16;
        const uint32_t d = sbase + p * K1_STGB + tid * 16;
#pragma unroll
        for (int c = 0; c < 4; ++c)
            CP_ASYNC16(d + c * 4096, g + c * 4096);
        CP_COMMIT();
    }

    // per-head scale = beta / max(||k_h||, eps)
    if (warp < HH) {
        const float4 kv = ((const float4*)(kq + (b * HH + warp) * MM))[lane];
        float ss = kv.x * kv.x + kv.y * kv.y + kv.z * kv.z + kv.w * kv.w;
#pragma unroll
        for (int o = 16; o > 0; o >>= 1)
            ss += __shfl_xor_sync(0xFFFFFFFFu, ss, o);
        if (lane == 0)
            scl[warp] = beta[b * HH + warp] / fmaxf(sqrtf(ss), 1e-8f);
    }

    // k into registers
    ulonglong2 kk[HH][4];
#pragma unroll
    for (int h = 0; h < HH; ++h)
#pragma unroll
        for (int j = 0; j < 4; ++j)
            kk[h][j] = *(const ulonglong2*)(kq + ((b * HH + h) << 7) + j * 32 + l8 * 4);

    __syncthreads();
    const float4 sc = make_float4(scl[0], scl[1], scl[2], scl[3]);
    const float gate = (l8 == 0) ? 1.0f : 0.0f;

    float4 es = make_float4(0, 0, 0, 0);

#pragma unroll
    for (int i = 0; i < 8; ++i) {
        if (i <= 3)      CP_WAIT(4);
        else if (i == 4) CP_WAIT(3);
        else if (i == 5) CP_WAIT(2);
        else if (i == 6) CP_WAIT(1);
        else             CP_WAIT(0);
        __syncthreads();

        const float* sp = stg + (i % K1_RING) * 4096 + (warp * 4 + r) * 128 + l8 * 4;

        u64 ss2 = 0, d2[HH] = {0, 0, 0, 0};
#pragma unroll
        for (int j = 0; j < 4; ++j) {
            const ulonglong2 v = *(const ulonglong2*)(sp + j * 32);
            ss2 = fma2(v.x, v.x, ss2);
            ss2 = fma2(v.y, v.y, ss2);
#pragma unroll
            for (int h = 0; h < HH; ++h) {
                d2[h] = fma2(v.x, kk[h][j].x, d2[h]);
                d2[h] = fma2(v.y, kk[h][j].y, d2[h]);
            }
        }

        float ssum = hadd2(ss2);
        float sd[HH];
#pragma unroll
        for (int h = 0; h < HH; ++h) sd[h] = hadd2(d2[h]);
#pragma unroll
        for (int o = 4; o > 0; o >>= 1) {
            ssum += __shfl_xor_sync(0xFFFFFFFFu, ssum, o);
#pragma unroll
            for (int h = 0; h < HH; ++h)
                sd[h] += __shfl_xor_sync(0xFFFFFFFFu, sd[h], o);
        }

        const float rmn = 1.0f / fmaxf(sqrtf(ssum), 1e-8f);
        const float4 lg = make_float4(sd[0] * rmn * sc.x, sd[1] * rmn * sc.y,
                                      sd[2] * rmn * sc.z, sd[3] * rmn * sc.w);
        const int s = srow0 + i * 32 + warp * 4 + r;
        if (l8 == 0)
            g_w[b * SS + s] = lg;

        // bounded logits: plain expsum, no max, no rescale chain
        es.x = fmaf(gate, __expf(lg.x), es.x);
        es.y = fmaf(gate, __expf(lg.y), es.y);
        es.z = fmaf(gate, __expf(lg.z), es.z);
        es.w = fmaf(gate, __expf(lg.w), es.w);

        if (i < 3) {
            const int p = i + 5;
            const char* gg = gbase + (size_t)p * K1_STGB + (size_t)tid * 16;
            const uint32_t d = sbase + (p % K1_RING) * K1_STGB + tid * 16;
#pragma unroll
            for (int c = 0; c < 4; ++c)
                CP_ASYNC16(d + c * 4096, gg + c * 4096);
            CP_COMMIT();
        }
    }

    // sum es across warp (gated lanes only are nonzero)
#pragma unroll
    for (int o = 16; o > 0; o >>= 1) {
        es.x += __shfl_xor_sync(0xFFFFFFFFu, es.x, o);
        es.y += __shfl_xor_sync(0xFFFFFFFFu, es.y, o);
        es.z += __shfl_xor_sync(0xFFFFFFFFu, es.z, o);
        es.w += __shfl_xor_sync(0xFFFFFFFFu, es.w, o);
    }
    if (lane == 0) ws8[warp] = es;
    __syncthreads();

    if (warp == 0 && lane < 8) {
        float4 s = ws8[lane];
#pragma unroll
        for (int o = 4; o > 0; o >>= 1) {
            s.x += __shfl_xor_sync(0xFFFFFFFFu, s.x, o);
            s.y += __shfl_xor_sync(0xFFFFFFFFu, s.y, o);
            s.z += __shfl_xor_sync(0xFFFFFFFFu, s.z, o);
            s.w += __shfl_xor_sync(0xFFFFFFFFu, s.w, o);
        }
        if (lane == 0)
            g_ps[b * 16 + tile] = s;
    }
}

// ---------------------------------------------------------------------------
// Kernel 2: normalize. grid 256 (8 chunks x 32 b), 512 threads.
// w = exp(logit) / S (no max needed). Zeroes out.
// ---------------------------------------------------------------------------
__global__ void __launch_bounds__(512) k2_norm(float* __restrict__ out) {
    const int b     = blockIdx.x >> 3;
    const int chunk = blockIdx.x & 7;
    const int tid   = threadIdx.x;

    __shared__ float4 sm_is;

    if (tid < 32) {
        float4 s4 = (tid < 16) ? g_ps[b * 16 + tid] : make_float4(0, 0, 0, 0);
#pragma unroll
        for (int o = 8; o > 0; o >>= 1) {
            s4.x += __shfl_xor_sync(0xFFFFFFFFu, s4.x, o);
            s4.y += __shfl_xor_sync(0xFFFFFFFFu, s4.y, o);
            s4.z += __shfl_xor_sync(0xFFFFFFFFu, s4.z, o);
            s4.w += __shfl_xor_sync(0xFFFFFFFFu, s4.w, o);
        }
        if (tid == 0)
            sm_is = make_float4(1.0f / s4.x, 1.0f / s4.y, 1.0f / s4.z, 1.0f / s4.w);
    }
    __syncthreads();

    const float4 is = sm_is;
    const int idx = b * SS + chunk * 512 + tid;
    float4 lg = g_w[idx];
    lg.x = __expf(lg.x) * is.x;
    lg.y = __expf(lg.y) * is.y;
    lg.z = __expf(lg.z) * is.z;
    lg.w = __expf(lg.w) * is.w;
    g_w[idx] = lg;

    if (chunk == 0)
        out[b * HH * MM + tid] = 0.0f;
}

// ---------------------------------------------------------------------------
// Kernel 3: fused write + read, cp.async 6-stage ring; mem rows AND w staged.
// One barrier per stage (ring distance 6 makes the top barrier sufficient).
// ---------------------------------------------------------------------------
#define K3_STRF 4224                  // stage stride in floats (4096 mem + 128 w)
#define K3_WOFF 4096
#define K3_RING 6

__global__ void __launch_bounds__(256, 2) k3_write_read(const float* __restrict__ mem,
                                                        const float* __restrict__ erase,
                                                        const float* __restrict__ add,
                                                        float* __restrict__ out) {
    extern __shared__ float stg[];           // K3_RING * K3_STRF floats
    __shared__ float acc[HH * MM];

    const int b    = blockIdx.y;
    const int tile = blockIdx.x;             // 16 tiles per b
    const int tid  = threadIdx.x;
    const int warp = tid >> 5;
    const int lane = tid & 31;

    const int srow0 = tile * 256;
    const char* gbase = (const char*)(mem + ((size_t)b * SS + srow0) * MM);
    const char* wgbase = (const char*)(&g_w[b * SS + srow0]);
    const uint32_t sbase = smem_u32(stg);

    // prologue: issue stages 0..4
#pragma unroll
    for (int p = 0; p < 5; ++p) {
        const char* g = gbase + (size_t)p * 16384 + (size_t)tid * 16;
        const uint32_t d = sbase + p * (K3_STRF * 4) + tid * 16;
#pragma unroll
        for (int c = 0; c < 4; ++c)
            CP_ASYNC16(d + c * 4096, g + c * 4096);
        if (tid < 32)
            CP_ASYNC16(sbase + p * (K3_STRF * 4) + K3_WOFF * 4 + tid * 16,
                       wgbase + (size_t)p * 512 + (size_t)tid * 16);
        CP_COMMIT();
    }

    for (int i = tid; i < HH * MM; i += 256)
        acc[i] = 0.0f;

    u64 ner2[HH][2], ar2[HH][2];
#pragma unroll
    for (int h = 0; h < HH; ++h) {
        const float4 e4 = __ldg((const float4*)(erase + (b * HH + h) * MM) + lane);
        const float4 a4 = __ldg((const float4*)(add   + (b * HH + h) * MM) + lane);
        ner2[h][0] = pack2(-e4.x, -e4.y);
        ner2[h][1] = pack2(-e4.z, -e4.w);
        ar2[h][0]  = pack2(a4.x, a4.y);
        ar2[h][1]  = pack2(a4.z, a4.w);
    }
    const u64 ones = pack2(1.0f, 1.0f);

    u64 racc[HH][2];
#pragma unroll
    for (int h = 0; h < HH; ++h) { racc[h][0] = 0; racc[h][1] = 0; }

#pragma unroll
    for (int i = 0; i < 8; ++i) {
        if (i <= 3)      CP_WAIT(4);
        else if (i == 4) CP_WAIT(3);
        else if (i == 5) CP_WAIT(2);
        else if (i == 6) CP_WAIT(1);
        else             CP_WAIT(0);
        __syncthreads();

        const float* sp = stg + (i % K3_RING) * K3_STRF;
#pragma unroll
        for (int q = 0; q < 4; ++q) {
            const int rl = warp * 4 + q;
            const ulonglong2 v = *(const ulonglong2*)(sp + rl * 128 + lane * 4);
            const float4 wq = *(const float4*)(sp + K3_WOFF + rl * 4);

            u64 w2[HH];
            w2[0] = pack2(wq.x, wq.x); w2[1] = pack2(wq.y, wq.y);
            w2[2] = pack2(wq.z, wq.z); w2[3] = pack2(wq.w, wq.w);

            u64 x0 = v.x, x1 = v.y;
#pragma unroll
            for (int h = 0; h < HH; ++h) {
                const u64 t0  = fma2(ner2[h][0], w2[h], ones);   // 1 - w*e
                const u64 t1  = fma2(ner2[h][1], w2[h], ones);
                const u64 wa0 = mul2(w2[h], ar2[h][0]);          // w*a
                const u64 wa1 = mul2(w2[h], ar2[h][1]);
                x0 = fma2(x0, t0, wa0);
                x1 = fma2(x1, t1, wa1);
            }
#pragma unroll
            for (int h = 0; h < HH; ++h) {
                racc[h][0] = fma2(w2[h], x0, racc[h][0]);
                racc[h][1] = fma2(w2[h], x1, racc[h][1]);
            }
        }

        if (i < 3) {
            const int p = i + 5;
            const char* g = gbase + (size_t)p * 16384 + (size_t)tid * 16;
            const uint32_t d = sbase + (p % K3_RING) * (K3_STRF * 4) + tid * 16;
#pragma unroll
            for (int c = 0; c < 4; ++c)
                CP_ASYNC16(d + c * 4096, g + c * 4096);
            if (tid < 32)
                CP_ASYNC16(sbase + (p % K3_RING) * (K3_STRF * 4) + K3_WOFF * 4 + tid * 16,
                           wgbase + (size_t)p * 512 + (size_t)tid * 16);
            CP_COMMIT();
        }
    }

#pragma unroll
    for (int h = 0; h < HH; ++h) {
        const float2 r0 = unpack2(racc[h][0]);
        const float2 r1 = unpack2(racc[h][1]);
        atomicAdd(&acc[h * MM + lane * 4 + 0], r0.x);
        atomicAdd(&acc[h * MM + lane * 4 + 1], r0.y);
        atomicAdd(&acc[h * MM + lane * 4 + 2], r1.x);
        atomicAdd(&acc[h * MM + lane * 4 + 3], r1.y);
    }
    __syncthreads();

    for (int i = tid; i < HH * MM; i += 256)
        atomicAdd(&out[b * HH * MM + i], acc[i]);
}

// ---------------------------------------------------------------------------
extern "C" void kernel_launch(void* const* d_in, const int* in_sizes, int n_in,
                              void* d_out, int out_size) {
    const float* mem   = (const float*)d_in[0];  // (B,S,M)
    const float* kq    = (const float*)d_in[1];  // (B,H,M)
    const float* beta  = (const float*)d_in[2];  // (B,H,1)
    const float* erase = (const float*)d_in[3];  // (B,H,M)
    const float* add   = (const float*)d_in[4];  // (B,H,M)
    float* out = (float*)d_out;                  // (B,H,M)

    (void)in_sizes; (void)n_in; (void)out_size;

    static bool attr_done = false;
    if (!attr_done) {
        cudaFuncSetAttribute(k1_dots, cudaFuncAttributeMaxDynamicSharedMemorySize,
                             K1_RING * K1_STGB);
        cudaFuncSetAttribute(k3_write_read, cudaFuncAttributeMaxDynamicSharedMemorySize,
                             K3_RING * K3_STRF * 4);
        attr_done = true;
    }

    k1_dots<<<BB * 16, 256, K1_RING * K1_STGB>>>(mem, kq, beta);
    k2_norm<<<BB * 8, 512>>>(out);
    k3_write_read<<<dim3(16, BB), 256, K3_RING * K3_STRF * 4>>>(mem, erase, add, out);
}

// round 15
// speedup vs baseline: 1.6110x; 1.0086x over previous
#include <cuda_runtime.h>
#include <cuda_bf16.h>
#include <cstdint>

#define BB 32
#define HH 4
#define SS 4096
#define MM 128

typedef unsigned long long u64;

__device__ __forceinline__ u64 fma2(u64 a, u64 b, u64 c) {
    u64 d; asm("fma.rn.f32x2 %0,%1,%2,%3;" : "=l"(d) : "l"(a), "l"(b), "l"(c)); return d;
}
__device__ __forceinline__ u64 mul2(u64 a, u64 b) {
    u64 d; asm("mul.rn.f32x2 %0,%1,%2;" : "=l"(d) : "l"(a), "l"(b)); return d;
}
__device__ __forceinline__ u64 pack2(float lo, float hi) {
    u64 r; asm("mov.b64 %0,{%1,%2};" : "=l"(r) : "f"(lo), "f"(hi)); return r;
}
__device__ __forceinline__ float2 unpack2(u64 x) {
    float2 f; asm("mov.b64 {%0,%1},%2;" : "=f"(f.x), "=f"(f.y) : "l"(x)); return f;
}
__device__ __forceinline__ float hadd2(u64 x) {
    const float2 f = unpack2(x); return f.x + f.y;
}
__device__ __forceinline__ uint32_t smem_u32(const void* p) {
    return (uint32_t)__cvta_generic_to_shared(p);
}

#define CP_ASYNC16(dst, src) \
    asm volatile("cp.async.cg.shared.global [%0], [%1], 16;" :: "r"(dst), "l"(src))
#define CP_COMMIT() asm volatile("cp.async.commit_group;")
#define CP_WAIT(n)  asm volatile("cp.async.wait_group %0;" :: "n"(n))

// Scratch
__device__ float4 g_w[BB * SS];    // scaled logits, then softmax weights
__device__ float4 g_ps[BB * 8];    // per-tile(512-row) expsum (4 heads)

// ---------------------------------------------------------------------------
// Kernel 1: cp.async 6-stage ring (32-row / 16KB stages), 512-row tile
// (grid 256 = ONE wave at 2 blocks/SM). Bounded logits => expsum only.
// 8 lanes/row, k in registers, 3-stage butterfly.
// ---------------------------------------------------------------------------
#define K1_TILE 512
#define K1_STGB 16384                 // stage bytes (32 rows * 512B)
#define K1_RING 6
#define K1_NSTG 16

__global__ void __launch_bounds__(256, 2) k1_dots(const float* __restrict__ mem,
                                                  const float* __restrict__ kq,
                                                  const float* __restrict__ beta) {
    extern __shared__ float stg[];           // K1_RING * 4096 floats
    __shared__ float  scl[HH];
    __shared__ float4 ws8[8];

    const int b    = blockIdx.x >> 3;        // 8 tiles per b
    const int tile = blockIdx.x & 7;
    const int tid  = threadIdx.x;
    const int warp = tid >> 5;
    const int lane = tid & 31;
    const int l8   = lane & 7;
    const int r    = lane >> 3;

    const int srow0 = tile * K1_TILE;
    const char* gbase = (const char*)(mem + ((size_t)b * SS + srow0) * MM);
    const uint32_t sbase = smem_u32(stg);

    // prologue: issue stages 0..4
#pragma unroll
    for (int p = 0; p < 5; ++p) {
        const char* g = gbase + (size_t)p * K1_STGB + (size_t)tid * 16;
        const uint32_t d = sbase + p * K1_STGB + tid * 16;
#pragma unroll
        for (int c = 0; c < 4; ++c)
            CP_ASYNC16(d + c * 4096, g + c * 4096);
        CP_COMMIT();
    }

    // per-head scale = beta / max(||k_h||, eps)
    if (warp < HH) {
        const float4 kv = ((const float4*)(kq + (b * HH + warp) * MM))[lane];
        float ss = kv.x * kv.x + kv.y * kv.y + kv.z * kv.z + kv.w * kv.w;
#pragma unroll
        for (int o = 16; o > 0; o >>= 1)
            ss += __shfl_xor_sync(0xFFFFFFFFu, ss, o);
        if (lane == 0)
            scl[warp] = beta[b * HH + warp] / fmaxf(sqrtf(ss), 1e-8f);
    }

    // k into registers
    ulonglong2 kk[HH][4];
#pragma unroll
    for (int h = 0; h < HH; ++h)
#pragma unroll
        for (int j = 0; j < 4; ++j)
            kk[h][j] = *(const ulonglong2*)(kq + ((b * HH + h) << 7) + j * 32 + l8 * 4);

    __syncthreads();
    const float4 sc = make_float4(scl[0], scl[1], scl[2], scl[3]);
    const float gate = (l8 == 0) ? 1.0f : 0.0f;

    float4 es = make_float4(0, 0, 0, 0);

    for (int i = 0; i < K1_NSTG; ++i) {
        CP_WAIT(4);                          // stage i retired (5+i committed)
        __syncthreads();

        const float* sp = stg + (i % K1_RING) * 4096 + (warp * 4 + r) * 128 + l8 * 4;

        u64 ss2 = 0, d2[HH] = {0, 0, 0, 0};
#pragma unroll
        for (int j = 0; j < 4; ++j) {
            const ulonglong2 v = *(const ulonglong2*)(sp + j * 32);
            ss2 = fma2(v.x, v.x, ss2);
            ss2 = fma2(v.y, v.y, ss2);
#pragma unroll
            for (int h = 0; h < HH; ++h) {
                d2[h] = fma2(v.x, kk[h][j].x, d2[h]);
                d2[h] = fma2(v.y, kk[h][j].y, d2[h]);
            }
        }

        float ssum = hadd2(ss2);
        float sd[HH];
#pragma unroll
        for (int h = 0; h < HH; ++h) sd[h] = hadd2(d2[h]);
#pragma unroll
        for (int o = 4; o > 0; o >>= 1) {
            ssum += __shfl_xor_sync(0xFFFFFFFFu, ssum, o);
#pragma unroll
            for (int h = 0; h < HH; ++h)
                sd[h] += __shfl_xor_sync(0xFFFFFFFFu, sd[h], o);
        }

        const float rmn = 1.0f / fmaxf(sqrtf(ssum), 1e-8f);
        const float4 lg = make_float4(sd[0] * rmn * sc.x, sd[1] * rmn * sc.y,
                                      sd[2] * rmn * sc.z, sd[3] * rmn * sc.w);
        const int s = srow0 + i * 32 + warp * 4 + r;
        if (l8 == 0)
            g_w[b * SS + s] = lg;

        // bounded logits: plain expsum, no max, no rescale chain
        es.x = fmaf(gate, __expf(lg.x), es.x);
        es.y = fmaf(gate, __expf(lg.y), es.y);
        es.z = fmaf(gate, __expf(lg.z), es.z);
        es.w = fmaf(gate, __expf(lg.w), es.w);

        // issue stage i+5 (commit EVERY iteration to keep wait math uniform)
        const int p = i + 5;
        if (p < K1_NSTG) {
            const char* gg = gbase + (size_t)p * K1_STGB + (size_t)tid * 16;
            const uint32_t d = sbase + (p % K1_RING) * K1_STGB + tid * 16;
#pragma unroll
            for (int c = 0; c < 4; ++c)
                CP_ASYNC16(d + c * 4096, gg + c * 4096);
        }
        CP_COMMIT();
    }

    // sum es across warp (gated lanes only are nonzero)
#pragma unroll
    for (int o = 16; o > 0; o >>= 1) {
        es.x += __shfl_xor_sync(0xFFFFFFFFu, es.x, o);
        es.y += __shfl_xor_sync(0xFFFFFFFFu, es.y, o);
        es.z += __shfl_xor_sync(0xFFFFFFFFu, es.z, o);
        es.w += __shfl_xor_sync(0xFFFFFFFFu, es.w, o);
    }
    if (lane == 0) ws8[warp] = es;
    __syncthreads();

    if (warp == 0 && lane < 8) {
        float4 s = ws8[lane];
#pragma unroll
        for (int o = 4; o > 0; o >>= 1) {
            s.x += __shfl_xor_sync(0xFFFFFFFFu, s.x, o);
            s.y += __shfl_xor_sync(0xFFFFFFFFu, s.y, o);
            s.z += __shfl_xor_sync(0xFFFFFFFFu, s.z, o);
            s.w += __shfl_xor_sync(0xFFFFFFFFu, s.w, o);
        }
        if (lane == 0)
            g_ps[b * 8 + tile] = s;
    }
}

// ---------------------------------------------------------------------------
// Kernel 2: normalize. grid 256 (8 chunks x 32 b), 512 threads.
// w = exp(logit) / S (no max needed). Zeroes out.
// ---------------------------------------------------------------------------
__global__ void __launch_bounds__(512) k2_norm(float* __restrict__ out) {
    const int b     = blockIdx.x >> 3;
    const int chunk = blockIdx.x & 7;
    const int tid   = threadIdx.x;

    __shared__ float4 sm_is;

    if (tid < 32) {
        float4 s4 = (tid < 8) ? g_ps[b * 8 + tid] : make_float4(0, 0, 0, 0);
#pragma unroll
        for (int o = 4; o > 0; o >>= 1) {
            s4.x += __shfl_xor_sync(0xFFFFFFFFu, s4.x, o);
            s4.y += __shfl_xor_sync(0xFFFFFFFFu, s4.y, o);
            s4.z += __shfl_xor_sync(0xFFFFFFFFu, s4.z, o);
            s4.w += __shfl_xor_sync(0xFFFFFFFFu, s4.w, o);
        }
        if (tid == 0)
            sm_is = make_float4(1.0f / s4.x, 1.0f / s4.y, 1.0f / s4.z, 1.0f / s4.w);
    }
    __syncthreads();

    const float4 is = sm_is;
    const int idx = b * SS + chunk * 512 + tid;
    float4 lg = g_w[idx];
    lg.x = __expf(lg.x) * is.x;
    lg.y = __expf(lg.y) * is.y;
    lg.z = __expf(lg.z) * is.z;
    lg.w = __expf(lg.w) * is.w;
    g_w[idx] = lg;

    if (chunk == 0)
        out[b * HH * MM + tid] = 0.0f;
}

// ---------------------------------------------------------------------------
// Kernel 3: fused write + read, cp.async 6-stage ring, 512-row tile
// (grid 256 = one wave); mem rows AND w staged; proven inner math.
// ---------------------------------------------------------------------------
#define K3_STRF 4224                  // stage stride in floats (4096 mem + 128 w)
#define K3_WOFF 4096
#define K3_RING 6
#define K3_NSTG 16

__global__ void __launch_bounds__(256, 2) k3_write_read(const float* __restrict__ mem,
                                                        const float* __restrict__ erase,
                                                        const float* __restrict__ add,
                                                        float* __restrict__ out) {
    extern __shared__ float stg[];           // K3_RING * K3_STRF floats
    __shared__ float acc[HH * MM];

    const int b    = blockIdx.y;
    const int tile = blockIdx.x;             // 8 tiles per b
    const int tid  = threadIdx.x;
    const int warp = tid >> 5;
    const int lane = tid & 31;

    const int srow0 = tile * 512;
    const char* gbase = (const char*)(mem + ((size_t)b * SS + srow0) * MM);
    const char* wgbase = (const char*)(&g_w[b * SS + srow0]);
    const uint32_t sbase = smem_u32(stg);

    // prologue: issue stages 0..4
#pragma unroll
    for (int p = 0; p < 5; ++p) {
        const char* g = gbase + (size_t)p * 16384 + (size_t)tid * 16;
        const uint32_t d = sbase + p * (K3_STRF * 4) + tid * 16;
#pragma unroll
        for (int c = 0; c < 4; ++c)
            CP_ASYNC16(d + c * 4096, g + c * 4096);
        if (tid < 32)
            CP_ASYNC16(sbase + p * (K3_STRF * 4) + K3_WOFF * 4 + tid * 16,
                       wgbase + (size_t)p * 512 + (size_t)tid * 16);
        CP_COMMIT();
    }

    for (int i = tid; i < HH * MM; i += 256)
        acc[i] = 0.0f;

    u64 ner2[HH][2], ar2[HH][2];
#pragma unroll
    for (int h = 0; h < HH; ++h) {
        const float4 e4 = __ldg((const float4*)(erase + (b * HH + h) * MM) + lane);
        const float4 a4 = __ldg((const float4*)(add   + (b * HH + h) * MM) + lane);
        ner2[h][0] = pack2(-e4.x, -e4.y);
        ner2[h][1] = pack2(-e4.z, -e4.w);
        ar2[h][0]  = pack2(a4.x, a4.y);
        ar2[h][1]  = pack2(a4.z, a4.w);
    }
    const u64 ones = pack2(1.0f, 1.0f);

    u64 racc[HH][2];
#pragma unroll
    for (int h = 0; h < HH; ++h) { racc[h][0] = 0; racc[h][1] = 0; }

    for (int i = 0; i < K3_NSTG; ++i) {
        CP_WAIT(4);
        __syncthreads();

        const float* sp = stg + (i % K3_RING) * K3_STRF;
#pragma unroll
        for (int q = 0; q < 4; ++q) {
            const int rl = warp * 4 + q;
            const ulonglong2 v = *(const ulonglong2*)(sp + rl * 128 + lane * 4);
            const float4 wq = *(const float4*)(sp + K3_WOFF + rl * 4);

            u64 w2[HH];
            w2[0] = pack2(wq.x, wq.x); w2[1] = pack2(wq.y, wq.y);
            w2[2] = pack2(wq.z, wq.z); w2[3] = pack2(wq.w, wq.w);

            u64 x0 = v.x, x1 = v.y;
#pragma unroll
            for (int h = 0; h < HH; ++h) {
                const u64 t0  = fma2(ner2[h][0], w2[h], ones);   // 1 - w*e
                const u64 t1  = fma2(ner2[h][1], w2[h], ones);
                const u64 wa0 = mul2(w2[h], ar2[h][0]);          // w*a
                const u64 wa1 = mul2(w2[h], ar2[h][1]);
                x0 = fma2(x0, t0, wa0);
                x1 = fma2(x1, t1, wa1);
            }
#pragma unroll
            for (int h = 0; h < HH; ++h) {
                racc[h][0] = fma2(w2[h], x0, racc[h][0]);
                racc[h][1] = fma2(w2[h], x1, racc[h][1]);
            }
        }

        const int p = i + 5;
        if (p < K3_NSTG) {
            const char* g = gbase + (size_t)p * 16384 + (size_t)tid * 16;
            const uint32_t d = sbase + (p % K3_RING) * (K3_STRF * 4) + tid * 16;
#pragma unroll
            for (int c = 0; c < 4; ++c)
                CP_ASYNC16(d + c * 4096, g + c * 4096);
            if (tid < 32)
                CP_ASYNC16(sbase + (p % K3_RING) * (K3_STRF * 4) + K3_WOFF * 4 + tid * 16,
                           wgbase + (size_t)p * 512 + (size_t)tid * 16);
        }
        CP_COMMIT();
    }

#pragma unroll
    for (int h = 0; h < HH; ++h) {
        const float2 r0 = unpack2(racc[h][0]);
        const float2 r1 = unpack2(racc[h][1]);
        atomicAdd(&acc[h * MM + lane * 4 + 0], r0.x);
        atomicAdd(&acc[h * MM + lane * 4 + 1], r0.y);
        atomicAdd(&acc[h * MM + lane * 4 + 2], r1.x);
        atomicAdd(&acc[h * MM + lane * 4 + 3], r1.y);
    }
    __syncthreads();

    for (int i = tid; i < HH * MM; i += 256)
        atomicAdd(&out[b * HH * MM + i], acc[i]);
}

// ---------------------------------------------------------------------------
extern "C" void kernel_launch(void* const* d_in, const int* in_sizes, int n_in,
                              void* d_out, int out_size) {
    const float* mem   = (const float*)d_in[0];  // (B,S,M)
    const float* kq    = (const float*)d_in[1];  // (B,H,M)
    const float* beta  = (const float*)d_in[2];  // (B,H,1)
    const float* erase = (const float*)d_in[3];  // (B,H,M)
    const float* add   = (const float*)d_in[4];  // (B,H,M)
    float* out = (float*)d_out;                  // (B,H,M)

    (void)in_sizes; (void)n_in; (void)out_size;

    static bool attr_done = false;
    if (!attr_done) {
        cudaFuncSetAttribute(k1_dots, cudaFuncAttributeMaxDynamicSharedMemorySize,
                             K1_RING * K1_STGB);
        cudaFuncSetAttribute(k3_write_read, cudaFuncAttributeMaxDynamicSharedMemorySize,
                             K3_RING * K3_STRF * 4);
        attr_done = true;
    }

    k1_dots<<<BB * 8, 256, K1_RING * K1_STGB>>>(mem, kq, beta);
    k2_norm<<<BB * 8, 512>>>(out);
    k3_write_read<<<dim3(8, BB), 256, K3_RING * K3_STRF * 4>>>(mem, erase, add, out);
}